// round 11
// baseline (speedup 1.0000x reference)
#include <cuda_runtime.h>
#include <cstdint>
#include <math.h>

// ---------------------------------------------------------------------------
// Problem constants
// ---------------------------------------------------------------------------
#define B_      8192
#define IN_     512
#define CTX_    256
#define CENTER_ 512
#define FF_     1024
#define RNN_    1024
#define OUT_    512
#define O2C_    256
#define TOT_    768

// ---------------------------------------------------------------------------
// Scratch (__device__ globals; allocation-free rule)
// ---------------------------------------------------------------------------
__device__ float  g_scale;
__device__ double g_npart[64];
__device__ float g_WpreT [FF_ * (IN_ + CTX_)];
__device__ float g_WxT   [RNN_ * FF_];
__device__ float g_WhT   [RNN_ * RNN_];
__device__ float g_WpostT[TOT_ * RNN_];
__device__ float g_WfT   [FF_ * CENTER_];
__device__ float g_WreadTf[CENTER_ * CTX_];
__device__ float g_rnn   [(size_t)B_ * FF_];

// ---------------------------------------------------------------------------
// Helpers
// ---------------------------------------------------------------------------
__device__ __forceinline__ uint32_t smem_u32(const void* p) {
    uint32_t a;
    asm("{ .reg .u64 t; cvta.to.shared.u64 t, %1; cvt.u32.u64 %0, t; }" : "=r"(a) : "l"(p));
    return a;
}
__device__ __forceinline__ uint32_t f2tf32(float x) {
    uint32_t o;
    asm("cvt.rna.tf32.f32 %0, %1;" : "=r"(o) : "f"(x));
    return o;
}
__device__ __forceinline__ void mma8(float* c, const uint32_t* a, const uint32_t* b) {
    asm volatile(
        "mma.sync.aligned.m16n8k8.row.col.f32.tf32.tf32.f32 "
        "{%0,%1,%2,%3}, {%4,%5,%6,%7}, {%8,%9}, {%0,%1,%2,%3};"
        : "+f"(c[0]), "+f"(c[1]), "+f"(c[2]), "+f"(c[3])
        : "r"(a[0]), "r"(a[1]), "r"(a[2]), "r"(a[3]), "r"(b[0]), "r"(b[1]));
}
__device__ __forceinline__ float fast_tanh(float x) {
    float e;
    asm("ex2.approx.f32 %0, %1;" : "=f"(e) : "f"(x * -2.885390081777927f));
    float r;
    asm("rcp.approx.f32 %0, %1;" : "=f"(r) : "f"(1.0f + e));
    return fmaf(2.0f, r, -1.0f);
}
#define CP_ASYNC16(sa, gp) \
    asm volatile("cp.async.cg.shared.global [%0], [%1], 16;" :: "r"(sa), "l"(gp))
#define CP_COMMIT() asm volatile("cp.async.commit_group;" ::: "memory")
#define CP_WAIT(N)  asm volatile("cp.async.wait_group %0;" :: "n"(N) : "memory")

// ---------------------------------------------------------------------------
// Norm (two-phase): g_scale = 1 / max(||W_read||_F, 1)
// ---------------------------------------------------------------------------
__global__ void norm_part(const float* __restrict__ W) {
    __shared__ double red[256];
    double s = 0.0;
    for (int i = blockIdx.x * 256 + threadIdx.x; i < CENTER_ * CTX_; i += 64 * 256) {
        float v = W[i];
        s += (double)v * (double)v;
    }
    red[threadIdx.x] = s;
    __syncthreads();
    for (int o = 128; o > 0; o >>= 1) {
        if (threadIdx.x < o) red[threadIdx.x] += red[threadIdx.x + o];
        __syncthreads();
    }
    if (threadIdx.x == 0) g_npart[blockIdx.x] = red[0];
}
__global__ void norm_fin() {
    __shared__ double red[64];
    red[threadIdx.x] = g_npart[threadIdx.x];
    __syncthreads();
    for (int o = 32; o > 0; o >>= 1) {
        if (threadIdx.x < o) red[threadIdx.x] += red[threadIdx.x + o];
        __syncthreads();
    }
    if (threadIdx.x == 0) g_scale = 1.0f / fmaxf((float)sqrt(red[0]), 1.0f);
}

// ---------------------------------------------------------------------------
// Elementwise tf32 rounding (only needed for W_read now)
// ---------------------------------------------------------------------------
__global__ void tf32_convert(const float* __restrict__ src, float* __restrict__ dst, int n4) {
    int i = blockIdx.x * (blockDim.x * 4) + threadIdx.x;
#pragma unroll
    for (int u = 0; u < 4; u++) {
        int idx = i + u * blockDim.x;
        if (idx < n4) {
            float4 v = ((const float4*)src)[idx];
            uint4 t;
            t.x = f2tf32(v.x); t.y = f2tf32(v.y); t.z = f2tf32(v.z); t.w = f2tf32(v.w);
            ((uint4*)dst)[idx] = t;
        }
    }
}

// ---------------------------------------------------------------------------
// Transpose with tf32 rounding: dst[C,R] = round(src[R,C]^T)
// ---------------------------------------------------------------------------
__global__ void transpose_kernel(const float* __restrict__ src, float* __restrict__ dst,
                                 int R, int C) {
    __shared__ float t[32][33];
    int bx = blockIdx.x * 32, by = blockIdx.y * 32;
#pragma unroll
    for (int i = 0; i < 32; i += 8)
        t[threadIdx.y + i][threadIdx.x] = src[(size_t)(by + threadIdx.y + i) * C + bx + threadIdx.x];
    __syncthreads();
#pragma unroll
    for (int i = 0; i < 32; i += 8)
        dst[(size_t)(bx + threadIdx.y + i) * R + by + threadIdx.x] =
            __uint_as_float(f2tf32(t[threadIdx.x][threadIdx.y + i]));
}

// ---------------------------------------------------------------------------
// tf32 mma.sync dual-segment GEMM (cp.async 3-stage pipeline, 512 threads)
//   D[M,N] = epi( A0@B0^T + A1@B1^T + bias )
//   BM=128, BN=256, KS=32; 16 warps as 4(M)x4(N); warp tile 32x64.
//   Swizzle (float granularity): col' = col ^ ((row&7)<<2)
//   Raw-fp32 A segments (cvtA=1): LDG before compute, cvt+STS after compute
//   (latency hidden; same ordering guarantees as cp.async via top barrier).
// ---------------------------------------------------------------------------
#define BM 128
#define BN 256
#define KS 32
#define NTHREADS 512
#define A_FLOATS     (BM * KS)            // 4096
#define STAGE_FLOATS ((BM + BN) * KS)     // 12288
#define STAGE_BYTES  (STAGE_FLOATS * 4)   // 49152
#define NSTAGE 3
#define SMEM_BYTES (NSTAGE * STAGE_BYTES) // 147456

#define EPI_SCALE      0
#define EPI_RELU       1
#define EPI_TANH       2
#define EPI_RELU_SPLIT 3

template <int EPI>
__global__ __launch_bounds__(NTHREADS, 1)
void tgemm(const float* __restrict__ A0, int lda0, const float* __restrict__ B0, int ldb0, int K0,
           const float* __restrict__ A1, int lda1, const float* __restrict__ B1, int ldb1, int K1,
           int cvtA0, int cvtA1,
           const float* __restrict__ bias,
           float* __restrict__ C0, float* __restrict__ C1, int NC, int splitN)
{
    extern __shared__ uint32_t smem[];
    const uint32_t sb = smem_u32(smem);

    const int tid = threadIdx.x;
    const int wid = tid >> 5;
    const int lid = tid & 31;
    const int g   = lid >> 2;
    const int tig = lid & 3;
    const int wm  = wid >> 2;       // 0..3  (M)
    const int wn  = wid & 3;        // 0..3  (N)
    const int rowBase = blockIdx.y * BM;
    const int colBase = blockIdx.x * BN;

    const int S0 = K0 / KS, S1 = K1 / KS, S = S0 + S1;

    // Loader assignments (512 threads)
    const int ar = tid >> 2, aq0 = (tid & 3) * 2;   // A: 128 rows x 8 quads; 2 quads/thread
    const int br = tid >> 1, bq0 = (tid & 1) * 4;   // B: 256 rows x 8 quads; 4 quads/thread
    uint32_t a_off[2], b_off[4];
#pragma unroll
    for (int i = 0; i < 2; i++)
        a_off[i] = (uint32_t)(ar * 32 + 4 * ((aq0 + i) ^ (ar & 7))) * 4u;
#pragma unroll
    for (int i = 0; i < 4; i++)
        b_off[i] = (uint32_t)(A_FLOATS + br * 32 + 4 * ((bq0 + i) ^ (br & 7))) * 4u;

    // Resolve segment for stage ns: returns per-thread gmem pointers + cvt flag
    auto resolve = [&](int ns, const float*& ap, const float*& bp, bool& cvt) {
        const float* A; const float* Bt; int la, lb, kb;
        if (ns < S0) { A = A0; Bt = B0; la = lda0; lb = ldb0; kb = ns * KS; cvt = (cvtA0 != 0); }
        else         { A = A1; Bt = B1; la = lda1; lb = ldb1; kb = (ns - S0) * KS; cvt = (cvtA1 != 0); }
        ap = A + (size_t)(rowBase + ar) * la + kb + aq0 * 4;
        bp = Bt + (size_t)(colBase + br) * lb + kb + bq0 * 4;
    };

    // Prologue (synchronous cvt is fine here): stages 0 and 1
#pragma unroll 1
    for (int ps = 0; ps < 2; ps++) {
        const float *ap, *bp; bool cvt;
        resolve(ps, ap, bp, cvt);
        const uint32_t base = sb + (uint32_t)ps * STAGE_BYTES;
#pragma unroll
        for (int i = 0; i < 4; i++) CP_ASYNC16(base + b_off[i], bp + 4 * i);
        if (!cvt) {
#pragma unroll
            for (int i = 0; i < 2; i++) CP_ASYNC16(base + a_off[i], ap + 4 * i);
        } else {
            char* cb = (char*)smem + ps * STAGE_BYTES;
#pragma unroll
            for (int i = 0; i < 2; i++) {
                const float4 v = *(const float4*)(ap + 4 * i);
                uint4 t;
                t.x = f2tf32(v.x); t.y = f2tf32(v.y); t.z = f2tf32(v.z); t.w = f2tf32(v.w);
                *(uint4*)(cb + a_off[i]) = t;
            }
        }
        CP_COMMIT();
    }

    float c[64];
#pragma unroll
    for (int i = 0; i < 64; i++) c[i] = 0.0f;

    for (int s = 0; s < S; s++) {
        const int buf = s % NSTAGE;
        CP_WAIT(1);            // stage s landed (this thread's copies)
        __syncthreads();       // publish stage s; retire all reads of buf (s+2)%3

        const int ns = s + 2;
        const bool pre = (ns < S);
        float4 ra0, ra1;
        bool cvt = false;
        if (pre) {
            const float *ap, *bp;
            resolve(ns, ap, bp, cvt);
            const uint32_t base = sb + (uint32_t)(ns % NSTAGE) * STAGE_BYTES;
#pragma unroll
            for (int i = 0; i < 4; i++) CP_ASYNC16(base + b_off[i], bp + 4 * i);
            if (!cvt) {
#pragma unroll
                for (int i = 0; i < 2; i++) CP_ASYNC16(base + a_off[i], ap + 4 * i);
            } else {
                ra0 = *(const float4*)ap;          // LDG issued; consumed after compute
                ra1 = *(const float4*)(ap + 4);
            }
        }
        CP_COMMIT();

        const uint32_t* As = smem + buf * STAGE_FLOATS;
        const uint32_t* Bs = As + A_FLOATS;

#pragma unroll
        for (int j = 0; j < 4; j++) {
            const int colX = (8 * j + tig) ^ (g << 2);
            const int colY = colX ^ 4;
            uint32_t af[2][4], bf[8][2];
#pragma unroll
            for (int t = 0; t < 2; t++) {
                const int r0 = wm * 32 + t * 16 + g;
                af[t][0] = As[r0 * 32 + colX];
                af[t][1] = As[(r0 + 8) * 32 + colX];
                af[t][2] = As[r0 * 32 + colY];
                af[t][3] = As[(r0 + 8) * 32 + colY];
            }
#pragma unroll
            for (int u = 0; u < 8; u++) {
                const int n0 = wn * 64 + u * 8 + g;
                bf[u][0] = Bs[n0 * 32 + colX];
                bf[u][1] = Bs[n0 * 32 + colY];
            }
#pragma unroll
            for (int t = 0; t < 2; t++)
#pragma unroll
                for (int u = 0; u < 8; u++)
                    mma8(&c[(t * 8 + u) * 4], af[t], bf[u]);
        }

        if (pre && cvt) {
            char* cb = (char*)smem + (ns % NSTAGE) * STAGE_BYTES;
            uint4 t0, t1;
            t0.x = f2tf32(ra0.x); t0.y = f2tf32(ra0.y); t0.z = f2tf32(ra0.z); t0.w = f2tf32(ra0.w);
            t1.x = f2tf32(ra1.x); t1.y = f2tf32(ra1.y); t1.z = f2tf32(ra1.z); t1.w = f2tf32(ra1.w);
            *(uint4*)(cb + a_off[0]) = t0;
            *(uint4*)(cb + a_off[1]) = t1;
        }
        // No bottom barrier: next iteration's top barrier provides the ordering.
    }

    // Epilogue. Round to tf32 when the result feeds another GEMM.
    constexpr bool ROUND = (EPI != EPI_RELU_SPLIT);
    const float scale = (EPI == EPI_SCALE) ? g_scale : 0.0f;
#pragma unroll
    for (int t = 0; t < 2; t++) {
        const int row0 = rowBase + wm * 32 + t * 16 + g;
#pragma unroll
        for (int u = 0; u < 8; u++) {
            const int col = colBase + wn * 64 + u * 8 + 2 * tig;
            float v0 = c[(t * 8 + u) * 4 + 0];
            float v1 = c[(t * 8 + u) * 4 + 1];
            float v2 = c[(t * 8 + u) * 4 + 2];
            float v3 = c[(t * 8 + u) * 4 + 3];
            if (EPI == EPI_SCALE) {
                v0 *= scale; v1 *= scale; v2 *= scale; v3 *= scale;
            } else {
                const float b0 = bias[col], b1 = bias[col + 1];
                v0 += b0; v1 += b1; v2 += b0; v3 += b1;
                if (EPI == EPI_RELU || EPI == EPI_RELU_SPLIT) {
                    v0 = fmaxf(v0, 0.0f); v1 = fmaxf(v1, 0.0f);
                    v2 = fmaxf(v2, 0.0f); v3 = fmaxf(v3, 0.0f);
                } else {
                    v0 = fast_tanh(v0); v1 = fast_tanh(v1);
                    v2 = fast_tanh(v2); v3 = fast_tanh(v3);
                }
            }
            if (ROUND) {
                v0 = __uint_as_float(f2tf32(v0));
                v1 = __uint_as_float(f2tf32(v1));
                v2 = __uint_as_float(f2tf32(v2));
                v3 = __uint_as_float(f2tf32(v3));
            }
            if (EPI != EPI_RELU_SPLIT) {
                *(float2*)&C0[(size_t)row0 * NC + col]       = make_float2(v0, v1);
                *(float2*)&C0[(size_t)(row0 + 8) * NC + col] = make_float2(v2, v3);
            } else {
                if (col < splitN) {
                    *(float2*)&C0[(size_t)row0 * splitN + col]       = make_float2(v0, v1);
                    *(float2*)&C0[(size_t)(row0 + 8) * splitN + col] = make_float2(v2, v3);
                } else {
                    const int c2 = col - splitN, w2 = NC - splitN;
                    *(float2*)&C1[(size_t)row0 * w2 + c2]       = make_float2(v0, v1);
                    *(float2*)&C1[(size_t)(row0 + 8) * w2 + c2] = make_float2(v2, v3);
                }
            }
        }
    }
}

// ---------------------------------------------------------------------------
// Launch
// ---------------------------------------------------------------------------
extern "C" void kernel_launch(void* const* d_in, const int* in_sizes, int n_in,
                              void* d_out, int out_size)
{
    const float* inputs = (const float*)d_in[0];
    const float* center = (const float*)d_in[1];
    const float* mstate = (const float*)d_in[2];
    const float* W_read = (const float*)d_in[3];
    const float* W_pre  = (const float*)d_in[4];
    const float* b_pre  = (const float*)d_in[5];
    const float* Wx     = (const float*)d_in[6];
    const float* Wh     = (const float*)d_in[7];
    const float* b_rnn  = (const float*)d_in[8];
    const float* W_post = (const float*)d_in[9];
    const float* b_post = (const float*)d_in[10];

    float* out  = (float*)d_out;
    float* net  = out;
    float* o2c  = out + (size_t)B_ * OUT_;
    float* hnew = out + (size_t)B_ * (OUT_ + O2C_);

    float *WpreT, *WxT, *WhT, *WpostT, *WfT, *WreadTf, *rnn;
    cudaGetSymbolAddress((void**)&WpreT,   g_WpreT);
    cudaGetSymbolAddress((void**)&WxT,     g_WxT);
    cudaGetSymbolAddress((void**)&WhT,     g_WhT);
    cudaGetSymbolAddress((void**)&WpostT,  g_WpostT);
    cudaGetSymbolAddress((void**)&WfT,     g_WfT);
    cudaGetSymbolAddress((void**)&WreadTf, g_WreadTf);
    cudaGetSymbolAddress((void**)&rnn,     g_rnn);

    cudaFuncSetAttribute(tgemm<EPI_SCALE>,      cudaFuncAttributeMaxDynamicSharedMemorySize, SMEM_BYTES);
    cudaFuncSetAttribute(tgemm<EPI_RELU>,       cudaFuncAttributeMaxDynamicSharedMemorySize, SMEM_BYTES);
    cudaFuncSetAttribute(tgemm<EPI_TANH>,       cudaFuncAttributeMaxDynamicSharedMemorySize, SMEM_BYTES);
    cudaFuncSetAttribute(tgemm<EPI_RELU_SPLIT>, cudaFuncAttributeMaxDynamicSharedMemorySize, SMEM_BYTES);

    dim3 tb(32, 8);

    norm_part<<<64, 256>>>(W_read);
    norm_fin<<<1, 64>>>();

    // Only W_read needs a standalone convert (B operand of GEMM1)
    tf32_convert<<<(CENTER_ * CTX_ / 4 + 1023) / 1024, 256>>>(W_read, WreadTf, CENTER_ * CTX_ / 4);

    transpose_kernel<<<dim3(FF_ / 32, (IN_ + CTX_) / 32), tb>>>(W_pre,  WpreT,  IN_ + CTX_, FF_);
    transpose_kernel<<<dim3(RNN_ / 32, FF_ / 32),  tb>>>(Wx,     WxT,    FF_,  RNN_);
    transpose_kernel<<<dim3(RNN_ / 32, RNN_ / 32), tb>>>(Wh,     WhT,    RNN_, RNN_);
    transpose_kernel<<<dim3(TOT_ / 32, RNN_ / 32), tb>>>(W_post, WpostT, RNN_, TOT_);

    // WfT = scale * (WpreT_ctx @ W_read^T)   (M=1024, N=512, K=256)
    tgemm<EPI_SCALE><<<dim3(CENTER_ / BN, FF_ / BM), NTHREADS, SMEM_BYTES>>>(
        WpreT + IN_, IN_ + CTX_, WreadTf, CTX_, CTX_,
        nullptr, 0, nullptr, 0, 0,
        0, 0,
        nullptr, WfT, nullptr, CENTER_, 0);

    // rnn_in = relu(inputs@Wpre[:512] + center@Wf + b_pre)  (M=8192,N=1024,K=512+512)
    tgemm<EPI_RELU><<<dim3(FF_ / BN, B_ / BM), NTHREADS, SMEM_BYTES>>>(
        inputs, IN_, WpreT, IN_ + CTX_, IN_,
        center, CENTER_, WfT, CENTER_, CENTER_,
        1, 1,
        b_pre, rnn, nullptr, FF_, 0);

    // h_new = tanh(rnn@Wx + mstate@Wh + b_rnn)  (M=8192,N=1024,K=1024+1024)
    tgemm<EPI_TANH><<<dim3(RNN_ / BN, B_ / BM), NTHREADS, SMEM_BYTES>>>(
        rnn, FF_, WxT, FF_, FF_,
        mstate, RNN_, WhT, RNN_, RNN_,
        0, 1,
        b_rnn, hnew, nullptr, RNN_, 0);

    // module_output = relu(h_new@W_post + b_post), split  (M=8192,N=768,K=1024)
    tgemm<EPI_RELU_SPLIT><<<dim3(TOT_ / BN, B_ / BM), NTHREADS, SMEM_BYTES>>>(
        hnew, RNN_, WpostT, RNN_, RNN_,
        nullptr, 0, nullptr, 0, 0,
        0, 0,
        b_post, net, o2c, TOT_, OUT_);
}

// round 12
// speedup vs baseline: 1.0111x; 1.0111x over previous
#include <cuda_runtime.h>
#include <cstdint>
#include <math.h>

// ---------------------------------------------------------------------------
// Problem constants
// ---------------------------------------------------------------------------
#define B_      8192
#define IN_     512
#define CTX_    256
#define CENTER_ 512
#define FF_     1024
#define RNN_    1024
#define OUT_    512
#define O2C_    256
#define TOT_    768

// ---------------------------------------------------------------------------
// Scratch (__device__ globals; allocation-free rule)
// ---------------------------------------------------------------------------
__device__ float  g_scale;
__device__ double g_npart[64];
__device__ float g_WpreT [FF_ * (IN_ + CTX_)];
__device__ float g_WxT   [RNN_ * FF_];
__device__ float g_WhT   [RNN_ * RNN_];
__device__ float g_WpostT[TOT_ * RNN_];
__device__ float g_WfT   [FF_ * CENTER_];
__device__ float g_WreadTf[CENTER_ * CTX_];
__device__ float g_inTf  [(size_t)B_ * IN_];
__device__ float g_ctrTf [(size_t)B_ * CENTER_];
__device__ float g_mstTf [(size_t)B_ * RNN_];
__device__ float g_rnn   [(size_t)B_ * FF_];

// ---------------------------------------------------------------------------
// Helpers
// ---------------------------------------------------------------------------
__device__ __forceinline__ uint32_t smem_u32(const void* p) {
    uint32_t a;
    asm("{ .reg .u64 t; cvta.to.shared.u64 t, %1; cvt.u32.u64 %0, t; }" : "=r"(a) : "l"(p));
    return a;
}
__device__ __forceinline__ uint32_t f2tf32(float x) {
    uint32_t o;
    asm("cvt.rna.tf32.f32 %0, %1;" : "=r"(o) : "f"(x));
    return o;
}
__device__ __forceinline__ void mma8(float* c, const uint32_t* a, const uint32_t* b) {
    asm volatile(
        "mma.sync.aligned.m16n8k8.row.col.f32.tf32.tf32.f32 "
        "{%0,%1,%2,%3}, {%4,%5,%6,%7}, {%8,%9}, {%0,%1,%2,%3};"
        : "+f"(c[0]), "+f"(c[1]), "+f"(c[2]), "+f"(c[3])
        : "r"(a[0]), "r"(a[1]), "r"(a[2]), "r"(a[3]), "r"(b[0]), "r"(b[1]));
}
__device__ __forceinline__ float fast_tanh(float x) {
    float e;
    asm("ex2.approx.f32 %0, %1;" : "=f"(e) : "f"(x * -2.885390081777927f));
    float r;
    asm("rcp.approx.f32 %0, %1;" : "=f"(r) : "f"(1.0f + e));
    return fmaf(2.0f, r, -1.0f);
}
#define CP_ASYNC16(sa, gp) \
    asm volatile("cp.async.cg.shared.global [%0], [%1], 16;" :: "r"(sa), "l"(gp))
#define CP_COMMIT() asm volatile("cp.async.commit_group;" ::: "memory")
#define CP_WAIT(N)  asm volatile("cp.async.wait_group %0;" :: "n"(N) : "memory")

// ---------------------------------------------------------------------------
// Norm (two-phase): g_scale = 1 / max(||W_read||_F, 1)
// ---------------------------------------------------------------------------
__global__ void norm_part(const float* __restrict__ W) {
    __shared__ double red[256];
    double s = 0.0;
    for (int i = blockIdx.x * 256 + threadIdx.x; i < CENTER_ * CTX_; i += 64 * 256) {
        float v = W[i];
        s += (double)v * (double)v;
    }
    red[threadIdx.x] = s;
    __syncthreads();
    for (int o = 128; o > 0; o >>= 1) {
        if (threadIdx.x < o) red[threadIdx.x] += red[threadIdx.x + o];
        __syncthreads();
    }
    if (threadIdx.x == 0) g_npart[blockIdx.x] = red[0];
}
__global__ void norm_fin() {
    __shared__ double red[64];
    red[threadIdx.x] = g_npart[threadIdx.x];
    __syncthreads();
    for (int o = 32; o > 0; o >>= 1) {
        if (threadIdx.x < o) red[threadIdx.x] += red[threadIdx.x + o];
        __syncthreads();
    }
    if (threadIdx.x == 0) g_scale = 1.0f / fmaxf((float)sqrt(red[0]), 1.0f);
}

// ---------------------------------------------------------------------------
// Elementwise tf32 rounding (float4 x4 grid-stride)
// ---------------------------------------------------------------------------
__global__ void tf32_convert(const float* __restrict__ src, float* __restrict__ dst, int n4) {
    int i = blockIdx.x * (blockDim.x * 4) + threadIdx.x;
#pragma unroll
    for (int u = 0; u < 4; u++) {
        int idx = i + u * blockDim.x;
        if (idx < n4) {
            float4 v = ((const float4*)src)[idx];
            uint4 t;
            t.x = f2tf32(v.x); t.y = f2tf32(v.y); t.z = f2tf32(v.z); t.w = f2tf32(v.w);
            ((uint4*)dst)[idx] = t;
        }
    }
}

// ---------------------------------------------------------------------------
// Transpose with tf32 rounding: dst[C,R] = round(src[R,C]^T)
// ---------------------------------------------------------------------------
__global__ void transpose_kernel(const float* __restrict__ src, float* __restrict__ dst,
                                 int R, int C) {
    __shared__ float t[32][33];
    int bx = blockIdx.x * 32, by = blockIdx.y * 32;
#pragma unroll
    for (int i = 0; i < 32; i += 8)
        t[threadIdx.y + i][threadIdx.x] = src[(size_t)(by + threadIdx.y + i) * C + bx + threadIdx.x];
    __syncthreads();
#pragma unroll
    for (int i = 0; i < 32; i += 8)
        dst[(size_t)(bx + threadIdx.y + i) * R + by + threadIdx.x] =
            __uint_as_float(f2tf32(t[threadIdx.x][threadIdx.y + i]));
}

// ---------------------------------------------------------------------------
// tf32 mma.sync dual-segment GEMM (cp.async 3-stage pipeline, 256 threads,
// 2 CTAs/SM for cross-CTA bubble filling)
//   D[M,N] = epi( A0@B0^T + A1@B1^T + bias )
//   BM=128, BN=128, KS=32; 8 warps as 4(M)x2(N); warp tile 32x64.
//   Swizzle (float granularity): col' = col ^ ((row&7)<<2)
//   Single barrier per stage (top barrier publishes stage s AND retires
//   reads of the buffer issue(s+2) overwrites).
// ---------------------------------------------------------------------------
#define BM 128
#define BN 128
#define KS 32
#define NTHREADS 256
#define A_FLOATS     (BM * KS)            // 4096
#define STAGE_FLOATS ((BM + BN) * KS)     // 8192
#define STAGE_BYTES  (STAGE_FLOATS * 4)   // 32768
#define NSTAGE 3
#define SMEM_BYTES (NSTAGE * STAGE_BYTES) // 98304

#define EPI_SCALE      0
#define EPI_RELU       1
#define EPI_TANH       2
#define EPI_RELU_SPLIT 3

template <int EPI>
__global__ __launch_bounds__(NTHREADS, 2)
void tgemm(const float* __restrict__ A0, int lda0, const float* __restrict__ B0, int ldb0, int K0,
           const float* __restrict__ A1, int lda1, const float* __restrict__ B1, int ldb1, int K1,
           const float* __restrict__ bias,
           float* __restrict__ C0, float* __restrict__ C1, int NC, int splitN)
{
    extern __shared__ uint32_t smem[];
    const uint32_t sb = smem_u32(smem);

    const int tid = threadIdx.x;
    const int wid = tid >> 5;
    const int lid = tid & 31;
    const int g   = lid >> 2;
    const int tig = lid & 3;
    const int wm  = wid >> 1;       // 0..3  (M)
    const int wn  = wid & 1;        // 0..1  (N)
    const int rowBase = blockIdx.y * BM;
    const int colBase = blockIdx.x * BN;

    const int S0 = K0 / KS, S1 = K1 / KS, S = S0 + S1;

    // Loader assignments (256 threads): A 128 rows x 8 quads -> 4 quads/thread;
    // B 128 rows x 8 quads -> 4 quads/thread.
    const int ar = tid >> 1, aq0 = (tid & 1) * 4;
    uint32_t a_off[4], b_off[4];
#pragma unroll
    for (int i = 0; i < 4; i++)
        a_off[i] = (uint32_t)(ar * 32 + 4 * ((aq0 + i) ^ (ar & 7))) * 4u;
#pragma unroll
    for (int i = 0; i < 4; i++)
        b_off[i] = (uint32_t)(A_FLOATS + ar * 32 + 4 * ((aq0 + i) ^ (ar & 7))) * 4u;

    auto issue = [&](int ns, int buf) {
        const float* A; const float* Bt; int la, lb, kb;
        if (ns < S0) { A = A0; Bt = B0; la = lda0; lb = ldb0; kb = ns * KS; }
        else         { A = A1; Bt = B1; la = lda1; lb = ldb1; kb = (ns - S0) * KS; }
        const float* ap = A + (size_t)(rowBase + ar) * la + kb + aq0 * 4;
        const float* bp = Bt + (size_t)(colBase + ar) * lb + kb + aq0 * 4;
        const uint32_t base = sb + (uint32_t)buf * STAGE_BYTES;
#pragma unroll
        for (int i = 0; i < 4; i++) CP_ASYNC16(base + a_off[i], ap + 4 * i);
#pragma unroll
        for (int i = 0; i < 4; i++) CP_ASYNC16(base + b_off[i], bp + 4 * i);
    };

    float c[64];
#pragma unroll
    for (int i = 0; i < 64; i++) c[i] = 0.0f;

    // Prologue: stages 0 and 1 in flight
    issue(0, 0); CP_COMMIT();
    issue(1, 1); CP_COMMIT();

    for (int s = 0; s < S; s++) {
        const int buf = s % NSTAGE;
        CP_WAIT(1);            // stage s landed (this thread's copies)
        __syncthreads();       // publish stage s; retire reads of buf (s+2)%3

        if (s + 2 < S) issue(s + 2, (s + 2) % NSTAGE);
        CP_COMMIT();           // keep group counts aligned (may be empty)

        const uint32_t* As = smem + buf * STAGE_FLOATS;
        const uint32_t* Bs = As + A_FLOATS;

#pragma unroll
        for (int j = 0; j < 4; j++) {
            const int colX = (8 * j + tig) ^ (g << 2);
            const int colY = colX ^ 4;
            uint32_t af[2][4], bf[8][2];
#pragma unroll
            for (int t = 0; t < 2; t++) {
                const int r0 = wm * 32 + t * 16 + g;
                af[t][0] = As[r0 * 32 + colX];
                af[t][1] = As[(r0 + 8) * 32 + colX];
                af[t][2] = As[r0 * 32 + colY];
                af[t][3] = As[(r0 + 8) * 32 + colY];
            }
#pragma unroll
            for (int u = 0; u < 8; u++) {
                const int n0 = wn * 64 + u * 8 + g;
                bf[u][0] = Bs[n0 * 32 + colX];
                bf[u][1] = Bs[n0 * 32 + colY];
            }
#pragma unroll
            for (int t = 0; t < 2; t++)
#pragma unroll
                for (int u = 0; u < 8; u++)
                    mma8(&c[(t * 8 + u) * 4], af[t], bf[u]);
        }
        // No bottom barrier: next iteration's top barrier provides the ordering.
    }

    // Epilogue. Round to tf32 when the result feeds another GEMM.
    constexpr bool ROUND = (EPI != EPI_RELU_SPLIT);
    const float scale = (EPI == EPI_SCALE) ? g_scale : 0.0f;
#pragma unroll
    for (int t = 0; t < 2; t++) {
        const int row0 = rowBase + wm * 32 + t * 16 + g;
#pragma unroll
        for (int u = 0; u < 8; u++) {
            const int col = colBase + wn * 64 + u * 8 + 2 * tig;
            float v0 = c[(t * 8 + u) * 4 + 0];
            float v1 = c[(t * 8 + u) * 4 + 1];
            float v2 = c[(t * 8 + u) * 4 + 2];
            float v3 = c[(t * 8 + u) * 4 + 3];
            if (EPI == EPI_SCALE) {
                v0 *= scale; v1 *= scale; v2 *= scale; v3 *= scale;
            } else {
                const float b0 = bias[col], b1 = bias[col + 1];
                v0 += b0; v1 += b1; v2 += b0; v3 += b1;
                if (EPI == EPI_RELU || EPI == EPI_RELU_SPLIT) {
                    v0 = fmaxf(v0, 0.0f); v1 = fmaxf(v1, 0.0f);
                    v2 = fmaxf(v2, 0.0f); v3 = fmaxf(v3, 0.0f);
                } else {
                    v0 = fast_tanh(v0); v1 = fast_tanh(v1);
                    v2 = fast_tanh(v2); v3 = fast_tanh(v3);
                }
            }
            if (ROUND) {
                v0 = __uint_as_float(f2tf32(v0));
                v1 = __uint_as_float(f2tf32(v1));
                v2 = __uint_as_float(f2tf32(v2));
                v3 = __uint_as_float(f2tf32(v3));
            }
            if (EPI != EPI_RELU_SPLIT) {
                *(float2*)&C0[(size_t)row0 * NC + col]       = make_float2(v0, v1);
                *(float2*)&C0[(size_t)(row0 + 8) * NC + col] = make_float2(v2, v3);
            } else {
                if (col < splitN) {
                    *(float2*)&C0[(size_t)row0 * splitN + col]       = make_float2(v0, v1);
                    *(float2*)&C0[(size_t)(row0 + 8) * splitN + col] = make_float2(v2, v3);
                } else {
                    const int c2 = col - splitN, w2 = NC - splitN;
                    *(float2*)&C1[(size_t)row0 * w2 + c2]       = make_float2(v0, v1);
                    *(float2*)&C1[(size_t)(row0 + 8) * w2 + c2] = make_float2(v2, v3);
                }
            }
        }
    }
}

// ---------------------------------------------------------------------------
// Launch
// ---------------------------------------------------------------------------
extern "C" void kernel_launch(void* const* d_in, const int* in_sizes, int n_in,
                              void* d_out, int out_size)
{
    const float* inputs = (const float*)d_in[0];
    const float* center = (const float*)d_in[1];
    const float* mstate = (const float*)d_in[2];
    const float* W_read = (const float*)d_in[3];
    const float* W_pre  = (const float*)d_in[4];
    const float* b_pre  = (const float*)d_in[5];
    const float* Wx     = (const float*)d_in[6];
    const float* Wh     = (const float*)d_in[7];
    const float* b_rnn  = (const float*)d_in[8];
    const float* W_post = (const float*)d_in[9];
    const float* b_post = (const float*)d_in[10];

    float* out  = (float*)d_out;
    float* net  = out;
    float* o2c  = out + (size_t)B_ * OUT_;
    float* hnew = out + (size_t)B_ * (OUT_ + O2C_);

    float *WpreT, *WxT, *WhT, *WpostT, *WfT, *WreadTf, *inTf, *ctrTf, *mstTf, *rnn;
    cudaGetSymbolAddress((void**)&WpreT,   g_WpreT);
    cudaGetSymbolAddress((void**)&WxT,     g_WxT);
    cudaGetSymbolAddress((void**)&WhT,     g_WhT);
    cudaGetSymbolAddress((void**)&WpostT,  g_WpostT);
    cudaGetSymbolAddress((void**)&WfT,     g_WfT);
    cudaGetSymbolAddress((void**)&WreadTf, g_WreadTf);
    cudaGetSymbolAddress((void**)&inTf,    g_inTf);
    cudaGetSymbolAddress((void**)&ctrTf,   g_ctrTf);
    cudaGetSymbolAddress((void**)&mstTf,   g_mstTf);
    cudaGetSymbolAddress((void**)&rnn,     g_rnn);

    cudaFuncSetAttribute(tgemm<EPI_SCALE>,      cudaFuncAttributeMaxDynamicSharedMemorySize, SMEM_BYTES);
    cudaFuncSetAttribute(tgemm<EPI_RELU>,       cudaFuncAttributeMaxDynamicSharedMemorySize, SMEM_BYTES);
    cudaFuncSetAttribute(tgemm<EPI_TANH>,       cudaFuncAttributeMaxDynamicSharedMemorySize, SMEM_BYTES);
    cudaFuncSetAttribute(tgemm<EPI_RELU_SPLIT>, cudaFuncAttributeMaxDynamicSharedMemorySize, SMEM_BYTES);

    dim3 tb(32, 8);

    norm_part<<<64, 256>>>(W_read);
    norm_fin<<<1, 64>>>();

    tf32_convert<<<(B_ * IN_ / 4 + 1023) / 1024, 256>>>(inputs, inTf, B_ * IN_ / 4);
    tf32_convert<<<(B_ * CENTER_ / 4 + 1023) / 1024, 256>>>(center, ctrTf, B_ * CENTER_ / 4);
    tf32_convert<<<(B_ * RNN_ / 4 + 1023) / 1024, 256>>>(mstate, mstTf, B_ * RNN_ / 4);
    tf32_convert<<<(CENTER_ * CTX_ / 4 + 1023) / 1024, 256>>>(W_read, WreadTf, CENTER_ * CTX_ / 4);

    transpose_kernel<<<dim3(FF_ / 32, (IN_ + CTX_) / 32), tb>>>(W_pre,  WpreT,  IN_ + CTX_, FF_);
    transpose_kernel<<<dim3(RNN_ / 32, FF_ / 32),  tb>>>(Wx,     WxT,    FF_,  RNN_);
    transpose_kernel<<<dim3(RNN_ / 32, RNN_ / 32), tb>>>(Wh,     WhT,    RNN_, RNN_);
    transpose_kernel<<<dim3(TOT_ / 32, RNN_ / 32), tb>>>(W_post, WpostT, RNN_, TOT_);

    // WfT = scale * (WpreT_ctx @ W_read^T)   (M=1024, N=512, K=256)
    tgemm<EPI_SCALE><<<dim3(CENTER_ / BN, FF_ / BM), NTHREADS, SMEM_BYTES>>>(
        WpreT + IN_, IN_ + CTX_, WreadTf, CTX_, CTX_,
        nullptr, 0, nullptr, 0, 0,
        nullptr, WfT, nullptr, CENTER_, 0);

    // rnn_in = relu(inputs@Wpre[:512] + center@Wf + b_pre)  (M=8192,N=1024,K=512+512)
    tgemm<EPI_RELU><<<dim3(FF_ / BN, B_ / BM), NTHREADS, SMEM_BYTES>>>(
        inTf, IN_, WpreT, IN_ + CTX_, IN_,
        ctrTf, CENTER_, WfT, CENTER_, CENTER_,
        b_pre, rnn, nullptr, FF_, 0);

    // h_new = tanh(rnn@Wx + mstate@Wh + b_rnn)  (M=8192,N=1024,K=1024+1024)
    tgemm<EPI_TANH><<<dim3(RNN_ / BN, B_ / BM), NTHREADS, SMEM_BYTES>>>(
        rnn, FF_, WxT, FF_, FF_,
        mstTf, RNN_, WhT, RNN_, RNN_,
        b_rnn, hnew, nullptr, RNN_, 0);

    // module_output = relu(h_new@W_post + b_post), split  (M=8192,N=768,K=1024)
    tgemm<EPI_RELU_SPLIT><<<dim3(TOT_ / BN, B_ / BM), NTHREADS, SMEM_BYTES>>>(
        hnew, RNN_, WpostT, RNN_, RNN_,
        nullptr, 0, nullptr, 0, 0,
        b_post, net, o2c, TOT_, OUT_);
}

// round 13
// speedup vs baseline: 1.0539x; 1.0424x over previous
#include <cuda_runtime.h>
#include <cstdint>
#include <math.h>

// ---------------------------------------------------------------------------
// Problem constants
// ---------------------------------------------------------------------------
#define B_      8192
#define IN_     512
#define CTX_    256
#define CENTER_ 512
#define FF_     1024
#define RNN_    1024
#define OUT_    512
#define O2C_    256
#define TOT_    768

// ---------------------------------------------------------------------------
// Scratch (__device__ globals; allocation-free rule)
// ---------------------------------------------------------------------------
__device__ float  g_scale;
__device__ double g_npart[64];
__device__ float g_WpreT [FF_ * (IN_ + CTX_)];   // [1024][768]
__device__ float g_WxT   [RNN_ * FF_];
__device__ float g_WhT   [RNN_ * RNN_];
__device__ float g_WpostT[TOT_ * RNN_];
__device__ float g_WreadT[CTX_ * CENTER_];       // [256][512] (W_read^T, rounded)
__device__ float g_ctx   [(size_t)B_ * CTX_];    // context (scaled, rounded)
__device__ float g_inTf  [(size_t)B_ * IN_];
__device__ float g_ctrTf [(size_t)B_ * CENTER_];
__device__ float g_mstTf [(size_t)B_ * RNN_];
__device__ float g_rnn   [(size_t)B_ * FF_];

// ---------------------------------------------------------------------------
// Helpers
// ---------------------------------------------------------------------------
__device__ __forceinline__ uint32_t smem_u32(const void* p) {
    uint32_t a;
    asm("{ .reg .u64 t; cvta.to.shared.u64 t, %1; cvt.u32.u64 %0, t; }" : "=r"(a) : "l"(p));
    return a;
}
__device__ __forceinline__ uint32_t f2tf32(float x) {
    uint32_t o;
    asm("cvt.rna.tf32.f32 %0, %1;" : "=r"(o) : "f"(x));
    return o;
}
__device__ __forceinline__ void mma8(float* c, const uint32_t* a, const uint32_t* b) {
    asm volatile(
        "mma.sync.aligned.m16n8k8.row.col.f32.tf32.tf32.f32 "
        "{%0,%1,%2,%3}, {%4,%5,%6,%7}, {%8,%9}, {%0,%1,%2,%3};"
        : "+f"(c[0]), "+f"(c[1]), "+f"(c[2]), "+f"(c[3])
        : "r"(a[0]), "r"(a[1]), "r"(a[2]), "r"(a[3]), "r"(b[0]), "r"(b[1]));
}
__device__ __forceinline__ float fast_tanh(float x) {
    float e;
    asm("ex2.approx.f32 %0, %1;" : "=f"(e) : "f"(x * -2.885390081777927f));
    float r;
    asm("rcp.approx.f32 %0, %1;" : "=f"(r) : "f"(1.0f + e));
    return fmaf(2.0f, r, -1.0f);
}
#define CP_ASYNC16(sa, gp) \
    asm volatile("cp.async.cg.shared.global [%0], [%1], 16;" :: "r"(sa), "l"(gp))
#define CP_COMMIT() asm volatile("cp.async.commit_group;" ::: "memory")
#define CP_WAIT(N)  asm volatile("cp.async.wait_group %0;" :: "n"(N) : "memory")

// ---------------------------------------------------------------------------
// Norm (two-phase): g_scale = 1 / max(||W_read||_F, 1)
// ---------------------------------------------------------------------------
__global__ void norm_part(const float* __restrict__ W) {
    __shared__ double red[256];
    double s = 0.0;
    for (int i = blockIdx.x * 256 + threadIdx.x; i < CENTER_ * CTX_; i += 64 * 256) {
        float v = W[i];
        s += (double)v * (double)v;
    }
    red[threadIdx.x] = s;
    __syncthreads();
    for (int o = 128; o > 0; o >>= 1) {
        if (threadIdx.x < o) red[threadIdx.x] += red[threadIdx.x + o];
        __syncthreads();
    }
    if (threadIdx.x == 0) g_npart[blockIdx.x] = red[0];
}
__global__ void norm_fin() {
    __shared__ double red[64];
    red[threadIdx.x] = g_npart[threadIdx.x];
    __syncthreads();
    for (int o = 32; o > 0; o >>= 1) {
        if (threadIdx.x < o) red[threadIdx.x] += red[threadIdx.x + o];
        __syncthreads();
    }
    if (threadIdx.x == 0) g_scale = 1.0f / fmaxf((float)sqrt(red[0]), 1.0f);
}

// ---------------------------------------------------------------------------
// Elementwise tf32 rounding (float4 x4 grid-stride)
// ---------------------------------------------------------------------------
__global__ void tf32_convert(const float* __restrict__ src, float* __restrict__ dst, int n4) {
    int i = blockIdx.x * (blockDim.x * 4) + threadIdx.x;
#pragma unroll
    for (int u = 0; u < 4; u++) {
        int idx = i + u * blockDim.x;
        if (idx < n4) {
            float4 v = ((const float4*)src)[idx];
            uint4 t;
            t.x = f2tf32(v.x); t.y = f2tf32(v.y); t.z = f2tf32(v.z); t.w = f2tf32(v.w);
            ((uint4*)dst)[idx] = t;
        }
    }
}

// ---------------------------------------------------------------------------
// Transpose with tf32 rounding: dst[C,R] = round(src[R,C]^T)
// ---------------------------------------------------------------------------
__global__ void transpose_kernel(const float* __restrict__ src, float* __restrict__ dst,
                                 int R, int C) {
    __shared__ float t[32][33];
    int bx = blockIdx.x * 32, by = blockIdx.y * 32;
#pragma unroll
    for (int i = 0; i < 32; i += 8)
        t[threadIdx.y + i][threadIdx.x] = src[(size_t)(by + threadIdx.y + i) * C + bx + threadIdx.x];
    __syncthreads();
#pragma unroll
    for (int i = 0; i < 32; i += 8)
        dst[(size_t)(bx + threadIdx.y + i) * R + by + threadIdx.x] =
            __uint_as_float(f2tf32(t[threadIdx.x][threadIdx.y + i]));
}

// ---------------------------------------------------------------------------
// tf32 mma.sync dual-segment GEMM (cp.async 3-stage pipeline, 256 threads,
// 2 CTAs/SM)
//   D[M,N] = epi( A0@B0^T + A1@B1^T + bias )
//   BM=128, BN=128, KS=32; 8 warps as 4(M)x2(N); warp tile 32x64.
//   Swizzle (float granularity): col' = col ^ ((row&7)<<2)
// ---------------------------------------------------------------------------
#define BM 128
#define BN 128
#define KS 32
#define NTHREADS 256
#define A_FLOATS     (BM * KS)            // 4096
#define STAGE_FLOATS ((BM + BN) * KS)     // 8192
#define STAGE_BYTES  (STAGE_FLOATS * 4)   // 32768
#define NSTAGE 3
#define SMEM_BYTES (NSTAGE * STAGE_BYTES) // 98304

#define EPI_SCALE      0
#define EPI_RELU       1
#define EPI_TANH       2
#define EPI_RELU_SPLIT 3

template <int EPI>
__global__ __launch_bounds__(NTHREADS, 2)
void tgemm(const float* __restrict__ A0, int lda0, const float* __restrict__ B0, int ldb0, int K0,
           const float* __restrict__ A1, int lda1, const float* __restrict__ B1, int ldb1, int K1,
           const float* __restrict__ bias,
           float* __restrict__ C0, float* __restrict__ C1, int NC, int splitN)
{
    extern __shared__ uint32_t smem[];
    const uint32_t sb = smem_u32(smem);

    const int tid = threadIdx.x;
    const int wid = tid >> 5;
    const int lid = tid & 31;
    const int g   = lid >> 2;
    const int tig = lid & 3;
    const int wm  = wid >> 1;       // 0..3  (M)
    const int wn  = wid & 1;        // 0..1  (N)
    const int rowBase = blockIdx.y * BM;
    const int colBase = blockIdx.x * BN;

    const int S0 = K0 / KS, S1 = K1 / KS, S = S0 + S1;

    // Loader assignments (256 threads): 4 quads/thread for both tiles
    const int ar = tid >> 1, aq0 = (tid & 1) * 4;
    uint32_t a_off[4], b_off[4];
#pragma unroll
    for (int i = 0; i < 4; i++)
        a_off[i] = (uint32_t)(ar * 32 + 4 * ((aq0 + i) ^ (ar & 7))) * 4u;
#pragma unroll
    for (int i = 0; i < 4; i++)
        b_off[i] = (uint32_t)(A_FLOATS + ar * 32 + 4 * ((aq0 + i) ^ (ar & 7))) * 4u;

    auto issue = [&](int ns, int buf) {
        const float* A; const float* Bt; int la, lb, kb;
        if (ns < S0) { A = A0; Bt = B0; la = lda0; lb = ldb0; kb = ns * KS; }
        else         { A = A1; Bt = B1; la = lda1; lb = ldb1; kb = (ns - S0) * KS; }
        const float* ap = A + (size_t)(rowBase + ar) * la + kb + aq0 * 4;
        const float* bp = Bt + (size_t)(colBase + ar) * lb + kb + aq0 * 4;
        const uint32_t base = sb + (uint32_t)buf * STAGE_BYTES;
#pragma unroll
        for (int i = 0; i < 4; i++) CP_ASYNC16(base + a_off[i], ap + 4 * i);
#pragma unroll
        for (int i = 0; i < 4; i++) CP_ASYNC16(base + b_off[i], bp + 4 * i);
    };

    float c[64];
#pragma unroll
    for (int i = 0; i < 64; i++) c[i] = 0.0f;

    // Prologue: stages 0 and 1 in flight
    issue(0, 0); CP_COMMIT();
    issue(1, 1); CP_COMMIT();

    for (int s = 0; s < S; s++) {
        const int buf = s % NSTAGE;
        CP_WAIT(1);            // stage s landed (this thread's copies)
        __syncthreads();       // publish stage s; retire reads of buf (s+2)%3

        if (s + 2 < S) issue(s + 2, (s + 2) % NSTAGE);
        CP_COMMIT();           // keep group counts aligned (may be empty)

        const uint32_t* As = smem + buf * STAGE_FLOATS;
        const uint32_t* Bs = As + A_FLOATS;

#pragma unroll
        for (int j = 0; j < 4; j++) {
            const int colX = (8 * j + tig) ^ (g << 2);
            const int colY = colX ^ 4;
            uint32_t af[2][4], bf[8][2];
#pragma unroll
            for (int t = 0; t < 2; t++) {
                const int r0 = wm * 32 + t * 16 + g;
                af[t][0] = As[r0 * 32 + colX];
                af[t][1] = As[(r0 + 8) * 32 + colX];
                af[t][2] = As[r0 * 32 + colY];
                af[t][3] = As[(r0 + 8) * 32 + colY];
            }
#pragma unroll
            for (int u = 0; u < 8; u++) {
                const int n0 = wn * 64 + u * 8 + g;
                bf[u][0] = Bs[n0 * 32 + colX];
                bf[u][1] = Bs[n0 * 32 + colY];
            }
#pragma unroll
            for (int t = 0; t < 2; t++)
#pragma unroll
                for (int u = 0; u < 8; u++)
                    mma8(&c[(t * 8 + u) * 4], af[t], bf[u]);
        }
        // No bottom barrier: next iteration's top barrier provides the ordering.
    }

    // Epilogue. Round to tf32 when the result feeds another GEMM.
    constexpr bool ROUND = (EPI != EPI_RELU_SPLIT);
    const float scale = (EPI == EPI_SCALE) ? g_scale : 0.0f;
#pragma unroll
    for (int t = 0; t < 2; t++) {
        const int row0 = rowBase + wm * 32 + t * 16 + g;
#pragma unroll
        for (int u = 0; u < 8; u++) {
            const int col = colBase + wn * 64 + u * 8 + 2 * tig;
            float v0 = c[(t * 8 + u) * 4 + 0];
            float v1 = c[(t * 8 + u) * 4 + 1];
            float v2 = c[(t * 8 + u) * 4 + 2];
            float v3 = c[(t * 8 + u) * 4 + 3];
            if (EPI == EPI_SCALE) {
                v0 *= scale; v1 *= scale; v2 *= scale; v3 *= scale;
            } else {
                const float b0 = bias[col], b1 = bias[col + 1];
                v0 += b0; v1 += b1; v2 += b0; v3 += b1;
                if (EPI == EPI_RELU || EPI == EPI_RELU_SPLIT) {
                    v0 = fmaxf(v0, 0.0f); v1 = fmaxf(v1, 0.0f);
                    v2 = fmaxf(v2, 0.0f); v3 = fmaxf(v3, 0.0f);
                } else {
                    v0 = fast_tanh(v0); v1 = fast_tanh(v1);
                    v2 = fast_tanh(v2); v3 = fast_tanh(v3);
                }
            }
            if (ROUND) {
                v0 = __uint_as_float(f2tf32(v0));
                v1 = __uint_as_float(f2tf32(v1));
                v2 = __uint_as_float(f2tf32(v2));
                v3 = __uint_as_float(f2tf32(v3));
            }
            if (EPI != EPI_RELU_SPLIT) {
                *(float2*)&C0[(size_t)row0 * NC + col]       = make_float2(v0, v1);
                *(float2*)&C0[(size_t)(row0 + 8) * NC + col] = make_float2(v2, v3);
            } else {
                if (col < splitN) {
                    *(float2*)&C0[(size_t)row0 * splitN + col]       = make_float2(v0, v1);
                    *(float2*)&C0[(size_t)(row0 + 8) * splitN + col] = make_float2(v2, v3);
                } else {
                    const int c2 = col - splitN, w2 = NC - splitN;
                    *(float2*)&C1[(size_t)row0 * w2 + c2]       = make_float2(v0, v1);
                    *(float2*)&C1[(size_t)(row0 + 8) * w2 + c2] = make_float2(v2, v3);
                }
            }
        }
    }
}

// ---------------------------------------------------------------------------
// Launch
// ---------------------------------------------------------------------------
extern "C" void kernel_launch(void* const* d_in, const int* in_sizes, int n_in,
                              void* d_out, int out_size)
{
    const float* inputs = (const float*)d_in[0];
    const float* center = (const float*)d_in[1];
    const float* mstate = (const float*)d_in[2];
    const float* W_read = (const float*)d_in[3];
    const float* W_pre  = (const float*)d_in[4];
    const float* b_pre  = (const float*)d_in[5];
    const float* Wx     = (const float*)d_in[6];
    const float* Wh     = (const float*)d_in[7];
    const float* b_rnn  = (const float*)d_in[8];
    const float* W_post = (const float*)d_in[9];
    const float* b_post = (const float*)d_in[10];

    float* out  = (float*)d_out;
    float* net  = out;
    float* o2c  = out + (size_t)B_ * OUT_;
    float* hnew = out + (size_t)B_ * (OUT_ + O2C_);

    float *WpreT, *WxT, *WhT, *WpostT, *WreadT, *ctx, *inTf, *ctrTf, *mstTf, *rnn;
    cudaGetSymbolAddress((void**)&WpreT,  g_WpreT);
    cudaGetSymbolAddress((void**)&WxT,    g_WxT);
    cudaGetSymbolAddress((void**)&WhT,    g_WhT);
    cudaGetSymbolAddress((void**)&WpostT, g_WpostT);
    cudaGetSymbolAddress((void**)&WreadT, g_WreadT);
    cudaGetSymbolAddress((void**)&ctx,    g_ctx);
    cudaGetSymbolAddress((void**)&inTf,   g_inTf);
    cudaGetSymbolAddress((void**)&ctrTf,  g_ctrTf);
    cudaGetSymbolAddress((void**)&mstTf,  g_mstTf);
    cudaGetSymbolAddress((void**)&rnn,    g_rnn);

    cudaFuncSetAttribute(tgemm<EPI_SCALE>,      cudaFuncAttributeMaxDynamicSharedMemorySize, SMEM_BYTES);
    cudaFuncSetAttribute(tgemm<EPI_RELU>,       cudaFuncAttributeMaxDynamicSharedMemorySize, SMEM_BYTES);
    cudaFuncSetAttribute(tgemm<EPI_TANH>,       cudaFuncAttributeMaxDynamicSharedMemorySize, SMEM_BYTES);
    cudaFuncSetAttribute(tgemm<EPI_RELU_SPLIT>, cudaFuncAttributeMaxDynamicSharedMemorySize, SMEM_BYTES);

    dim3 tb(32, 8);

    norm_part<<<64, 256>>>(W_read);
    norm_fin<<<1, 64>>>();

    tf32_convert<<<(B_ * IN_ / 4 + 1023) / 1024, 256>>>(inputs, inTf, B_ * IN_ / 4);
    tf32_convert<<<(B_ * CENTER_ / 4 + 1023) / 1024, 256>>>(center, ctrTf, B_ * CENTER_ / 4);
    tf32_convert<<<(B_ * RNN_ / 4 + 1023) / 1024, 256>>>(mstate, mstTf, B_ * RNN_ / 4);

    transpose_kernel<<<dim3(FF_ / 32, (IN_ + CTX_) / 32), tb>>>(W_pre,  WpreT,  IN_ + CTX_, FF_);
    transpose_kernel<<<dim3(RNN_ / 32, FF_ / 32),  tb>>>(Wx,     WxT,    FF_,  RNN_);
    transpose_kernel<<<dim3(RNN_ / 32, RNN_ / 32), tb>>>(Wh,     WhT,    RNN_, RNN_);
    transpose_kernel<<<dim3(TOT_ / 32, RNN_ / 32), tb>>>(W_post, WpostT, RNN_, TOT_);
    transpose_kernel<<<dim3(CTX_ / 32, CENTER_ / 32), tb>>>(W_read, WreadT, CENTER_, CTX_);

    // ctx = scale * (center @ W_read)   (M=8192, N=256, K=512)
    tgemm<EPI_SCALE><<<dim3(CTX_ / BN, B_ / BM), NTHREADS, SMEM_BYTES>>>(
        ctrTf, CENTER_, WreadT, CENTER_, CENTER_,
        nullptr, 0, nullptr, 0, 0,
        nullptr, ctx, nullptr, CTX_, 0);

    // rnn_in = relu(inputs@Wpre[:512] + ctx@Wpre[512:768] + b_pre)
    //   (M=8192, N=1024, K=512+256)
    tgemm<EPI_RELU><<<dim3(FF_ / BN, B_ / BM), NTHREADS, SMEM_BYTES>>>(
        inTf, IN_, WpreT, IN_ + CTX_, IN_,
        ctx, CTX_, WpreT + IN_, IN_ + CTX_, CTX_,
        b_pre, rnn, nullptr, FF_, 0);

    // h_new = tanh(rnn@Wx + mstate@Wh + b_rnn)  (M=8192,N=1024,K=1024+1024)
    tgemm<EPI_TANH><<<dim3(RNN_ / BN, B_ / BM), NTHREADS, SMEM_BYTES>>>(
        rnn, FF_, WxT, FF_, FF_,
        mstTf, RNN_, WhT, RNN_, RNN_,
        b_rnn, hnew, nullptr, RNN_, 0);

    // module_output = relu(h_new@W_post + b_post), split  (M=8192,N=768,K=1024)
    tgemm<EPI_RELU_SPLIT><<<dim3(TOT_ / BN, B_ / BM), NTHREADS, SMEM_BYTES>>>(
        hnew, RNN_, WpostT, RNN_, RNN_,
        nullptr, 0, nullptr, 0, 0,
        b_post, net, o2c, TOT_, OUT_);
}

// round 14
// speedup vs baseline: 1.0723x; 1.0174x over previous
#include <cuda_runtime.h>
#include <cstdint>
#include <math.h>

// ---------------------------------------------------------------------------
// Problem constants
// ---------------------------------------------------------------------------
#define B_      8192
#define IN_     512
#define CTX_    256
#define CENTER_ 512
#define FF_     1024
#define RNN_    1024
#define OUT_    512
#define O2C_    256
#define TOT_    768

// ---------------------------------------------------------------------------
// Scratch (__device__ globals; allocation-free rule)
// ---------------------------------------------------------------------------
__device__ float  g_scale;
__device__ double g_npart[64];
__device__ float g_WpreT [FF_ * (IN_ + CTX_)];   // [1024][768]
__device__ float g_WxT   [RNN_ * FF_];
__device__ float g_WhT   [RNN_ * RNN_];
__device__ float g_WpostT[TOT_ * RNN_];
__device__ float g_WreadT[CTX_ * CENTER_];       // [256][512]
__device__ float g_ctx   [(size_t)B_ * CTX_];
__device__ float g_inTf  [(size_t)B_ * IN_];
__device__ float g_ctrTf [(size_t)B_ * CENTER_];
__device__ float g_mstTf [(size_t)B_ * RNN_];
__device__ float g_rnn   [(size_t)B_ * FF_];

// ---------------------------------------------------------------------------
// Helpers
// ---------------------------------------------------------------------------
__device__ __forceinline__ uint32_t smem_u32(const void* p) {
    uint32_t a;
    asm("{ .reg .u64 t; cvta.to.shared.u64 t, %1; cvt.u32.u64 %0, t; }" : "=r"(a) : "l"(p));
    return a;
}
__device__ __forceinline__ uint32_t f2tf32(float x) {
    uint32_t o;
    asm("cvt.rna.tf32.f32 %0, %1;" : "=r"(o) : "f"(x));
    return o;
}
__device__ __forceinline__ void mma8(float* c, const uint32_t* a, const uint32_t* b) {
    asm volatile(
        "mma.sync.aligned.m16n8k8.row.col.f32.tf32.tf32.f32 "
        "{%0,%1,%2,%3}, {%4,%5,%6,%7}, {%8,%9}, {%0,%1,%2,%3};"
        : "+f"(c[0]), "+f"(c[1]), "+f"(c[2]), "+f"(c[3])
        : "r"(a[0]), "r"(a[1]), "r"(a[2]), "r"(a[3]), "r"(b[0]), "r"(b[1]));
}
__device__ __forceinline__ float fast_tanh(float x) {
    float e;
    asm("ex2.approx.f32 %0, %1;" : "=f"(e) : "f"(x * -2.885390081777927f));
    float r;
    asm("rcp.approx.f32 %0, %1;" : "=f"(r) : "f"(1.0f + e));
    return fmaf(2.0f, r, -1.0f);
}
#define CP_ASYNC16(sa, gp) \
    asm volatile("cp.async.cg.shared.global [%0], [%1], 16;" :: "r"(sa), "l"(gp))
#define CP_COMMIT() asm volatile("cp.async.commit_group;" ::: "memory")
#define CP_WAIT(N)  asm volatile("cp.async.wait_group %0;" :: "n"(N) : "memory")

// ---------------------------------------------------------------------------
// Norm (two-phase): g_scale = 1 / max(||W_read||_F, 1)
// ---------------------------------------------------------------------------
__global__ void norm_part(const float* __restrict__ W) {
    __shared__ double red[256];
    double s = 0.0;
    for (int i = blockIdx.x * 256 + threadIdx.x; i < CENTER_ * CTX_; i += 64 * 256) {
        float v = W[i];
        s += (double)v * (double)v;
    }
    red[threadIdx.x] = s;
    __syncthreads();
    for (int o = 128; o > 0; o >>= 1) {
        if (threadIdx.x < o) red[threadIdx.x] += red[threadIdx.x + o];
        __syncthreads();
    }
    if (threadIdx.x == 0) g_npart[blockIdx.x] = red[0];
}
__global__ void norm_fin() {
    __shared__ double red[64];
    red[threadIdx.x] = g_npart[threadIdx.x];
    __syncthreads();
    for (int o = 32; o > 0; o >>= 1) {
        if (threadIdx.x < o) red[threadIdx.x] += red[threadIdx.x + o];
        __syncthreads();
    }
    if (threadIdx.x == 0) g_scale = 1.0f / fmaxf((float)sqrt(red[0]), 1.0f);
}

// ---------------------------------------------------------------------------
// Merged tf32 rounding for the 3 activation tensors (one launch)
// ---------------------------------------------------------------------------
#define CV_T1 (B_ * IN_ / 4)                 // 1,048,576 float4
#define CV_T2 (CV_T1 + B_ * CENTER_ / 4)     // 2,097,152
#define CV_T3 (CV_T2 + B_ * RNN_ / 4)        // 4,194,304

__global__ void conv_all(const float* __restrict__ in, const float* __restrict__ ctr,
                         const float* __restrict__ mst,
                         float* __restrict__ din, float* __restrict__ dctr,
                         float* __restrict__ dmst) {
    int i = blockIdx.x * (blockDim.x * 4) + threadIdx.x;
#pragma unroll
    for (int u = 0; u < 4; u++) {
        int idx = i + u * blockDim.x;
        if (idx < CV_T3) {
            const float4* s; uint4* d; int o;
            if (idx < CV_T1)      { s = (const float4*)in;  d = (uint4*)din;  o = idx; }
            else if (idx < CV_T2) { s = (const float4*)ctr; d = (uint4*)dctr; o = idx - CV_T1; }
            else                  { s = (const float4*)mst; d = (uint4*)dmst; o = idx - CV_T2; }
            float4 v = s[o];
            uint4 t;
            t.x = f2tf32(v.x); t.y = f2tf32(v.y); t.z = f2tf32(v.z); t.w = f2tf32(v.w);
            d[o] = t;
        }
    }
}

// ---------------------------------------------------------------------------
// Batched transpose with tf32 rounding (all 5 weight matrices, one launch)
//   job dims are compile-time; flat grid with range dispatch.
// ---------------------------------------------------------------------------
#define TJ0 768    // W_pre   [768,1024]:  (1024/32)*(768/32)
#define TJ1 (TJ0 + 1024)  // Wx [1024,1024]
#define TJ2 (TJ1 + 1024)  // Wh
#define TJ3 (TJ2 + 768)   // W_post [1024,768]
#define TJ4 (TJ3 + 128)   // W_read [512,256]: (256/32)*(512/32)

__global__ void transpose_all(const float* __restrict__ Wpre, const float* __restrict__ Wx,
                              const float* __restrict__ Wh,   const float* __restrict__ Wpost,
                              const float* __restrict__ Wread,
                              float* __restrict__ dWpre, float* __restrict__ dWx,
                              float* __restrict__ dWh,   float* __restrict__ dWpost,
                              float* __restrict__ dWread) {
    __shared__ float t[32][33];
    int b = blockIdx.x;
    const float* src; float* dst; int R, C, nbx;
    if (b < TJ0)      { src = Wpre;  dst = dWpre;  R = 768;  C = 1024; nbx = 32; }
    else if (b < TJ1) { b -= TJ0; src = Wx;    dst = dWx;    R = 1024; C = 1024; nbx = 32; }
    else if (b < TJ2) { b -= TJ1; src = Wh;    dst = dWh;    R = 1024; C = 1024; nbx = 32; }
    else if (b < TJ3) { b -= TJ2; src = Wpost; dst = dWpost; R = 1024; C = 768;  nbx = 24; }
    else              { b -= TJ3; src = Wread; dst = dWread; R = 512;  C = 256;  nbx = 8;  }
    int bx = (b % nbx) * 32, by = (b / nbx) * 32;
#pragma unroll
    for (int i = 0; i < 32; i += 8)
        t[threadIdx.y + i][threadIdx.x] = src[(size_t)(by + threadIdx.y + i) * C + bx + threadIdx.x];
    __syncthreads();
#pragma unroll
    for (int i = 0; i < 32; i += 8)
        dst[(size_t)(bx + threadIdx.y + i) * R + by + threadIdx.x] =
            __uint_as_float(f2tf32(t[threadIdx.x][threadIdx.y + i]));
}

// ---------------------------------------------------------------------------
// tf32 mma.sync dual-segment GEMM (cp.async 3-stage pipeline, 256 threads,
// 2 CTAs/SM)
//   D[M,N] = epi( A0@B0^T + A1@B1^T + bias )
//   BM=128, BN=128, KS=32; 8 warps as 4(M)x2(N); warp tile 32x64.
//   Swizzle (float granularity): col' = col ^ ((row&7)<<2)
// ---------------------------------------------------------------------------
#define BM 128
#define BN 128
#define KS 32
#define NTHREADS 256
#define A_FLOATS     (BM * KS)            // 4096
#define STAGE_FLOATS ((BM + BN) * KS)     // 8192
#define STAGE_BYTES  (STAGE_FLOATS * 4)   // 32768
#define NSTAGE 3
#define SMEM_BYTES (NSTAGE * STAGE_BYTES) // 98304

#define EPI_SCALE      0
#define EPI_RELU       1
#define EPI_TANH       2
#define EPI_RELU_SPLIT 3

template <int EPI>
__global__ __launch_bounds__(NTHREADS, 2)
void tgemm(const float* __restrict__ A0, int lda0, const float* __restrict__ B0, int ldb0, int K0,
           const float* __restrict__ A1, int lda1, const float* __restrict__ B1, int ldb1, int K1,
           const float* __restrict__ bias,
           float* __restrict__ C0, float* __restrict__ C1, int NC, int splitN)
{
    extern __shared__ uint32_t smem[];
    const uint32_t sb = smem_u32(smem);

    const int tid = threadIdx.x;
    const int wid = tid >> 5;
    const int lid = tid & 31;
    const int g   = lid >> 2;
    const int tig = lid & 3;
    const int wm  = wid >> 1;       // 0..3  (M)
    const int wn  = wid & 1;        // 0..1  (N)
    const int rowBase = blockIdx.y * BM;
    const int colBase = blockIdx.x * BN;

    const int S0 = K0 / KS, S1 = K1 / KS, S = S0 + S1;

    // Loader assignments (256 threads): 4 quads/thread for both tiles
    const int ar = tid >> 1, aq0 = (tid & 1) * 4;
    uint32_t a_off[4], b_off[4];
#pragma unroll
    for (int i = 0; i < 4; i++)
        a_off[i] = (uint32_t)(ar * 32 + 4 * ((aq0 + i) ^ (ar & 7))) * 4u;
#pragma unroll
    for (int i = 0; i < 4; i++)
        b_off[i] = (uint32_t)(A_FLOATS + ar * 32 + 4 * ((aq0 + i) ^ (ar & 7))) * 4u;

    auto issue = [&](int ns, int buf) {
        const float* A; const float* Bt; int la, lb, kb;
        if (ns < S0) { A = A0; Bt = B0; la = lda0; lb = ldb0; kb = ns * KS; }
        else         { A = A1; Bt = B1; la = lda1; lb = ldb1; kb = (ns - S0) * KS; }
        const float* ap = A + (size_t)(rowBase + ar) * la + kb + aq0 * 4;
        const float* bp = Bt + (size_t)(colBase + ar) * lb + kb + aq0 * 4;
        const uint32_t base = sb + (uint32_t)buf * STAGE_BYTES;
#pragma unroll
        for (int i = 0; i < 4; i++) CP_ASYNC16(base + a_off[i], ap + 4 * i);
#pragma unroll
        for (int i = 0; i < 4; i++) CP_ASYNC16(base + b_off[i], bp + 4 * i);
    };

    float c[64];
#pragma unroll
    for (int i = 0; i < 64; i++) c[i] = 0.0f;

    // Prologue: stages 0 and 1 in flight
    issue(0, 0); CP_COMMIT();
    issue(1, 1); CP_COMMIT();

    for (int s = 0; s < S; s++) {
        const int buf = s % NSTAGE;
        CP_WAIT(1);            // stage s landed (this thread's copies)
        __syncthreads();       // publish stage s; retire reads of buf (s+2)%3

        if (s + 2 < S) issue(s + 2, (s + 2) % NSTAGE);
        CP_COMMIT();           // keep group counts aligned (may be empty)

        const uint32_t* As = smem + buf * STAGE_FLOATS;
        const uint32_t* Bs = As + A_FLOATS;

#pragma unroll
        for (int j = 0; j < 4; j++) {
            const int colX = (8 * j + tig) ^ (g << 2);
            const int colY = colX ^ 4;
            uint32_t af[2][4], bf[8][2];
#pragma unroll
            for (int t = 0; t < 2; t++) {
                const int r0 = wm * 32 + t * 16 + g;
                af[t][0] = As[r0 * 32 + colX];
                af[t][1] = As[(r0 + 8) * 32 + colX];
                af[t][2] = As[r0 * 32 + colY];
                af[t][3] = As[(r0 + 8) * 32 + colY];
            }
#pragma unroll
            for (int u = 0; u < 8; u++) {
                const int n0 = wn * 64 + u * 8 + g;
                bf[u][0] = Bs[n0 * 32 + colX];
                bf[u][1] = Bs[n0 * 32 + colY];
            }
#pragma unroll
            for (int t = 0; t < 2; t++)
#pragma unroll
                for (int u = 0; u < 8; u++)
                    mma8(&c[(t * 8 + u) * 4], af[t], bf[u]);
        }
        // No bottom barrier: next iteration's top barrier provides the ordering.
    }

    // Epilogue. Round to tf32 when the result feeds another GEMM.
    constexpr bool ROUND = (EPI != EPI_RELU_SPLIT);
    const float scale = (EPI == EPI_SCALE) ? g_scale : 0.0f;
#pragma unroll
    for (int t = 0; t < 2; t++) {
        const int row0 = rowBase + wm * 32 + t * 16 + g;
#pragma unroll
        for (int u = 0; u < 8; u++) {
            const int col = colBase + wn * 64 + u * 8 + 2 * tig;
            float v0 = c[(t * 8 + u) * 4 + 0];
            float v1 = c[(t * 8 + u) * 4 + 1];
            float v2 = c[(t * 8 + u) * 4 + 2];
            float v3 = c[(t * 8 + u) * 4 + 3];
            if (EPI == EPI_SCALE) {
                v0 *= scale; v1 *= scale; v2 *= scale; v3 *= scale;
            } else {
                const float b0 = bias[col], b1 = bias[col + 1];
                v0 += b0; v1 += b1; v2 += b0; v3 += b1;
                if (EPI == EPI_RELU || EPI == EPI_RELU_SPLIT) {
                    v0 = fmaxf(v0, 0.0f); v1 = fmaxf(v1, 0.0f);
                    v2 = fmaxf(v2, 0.0f); v3 = fmaxf(v3, 0.0f);
                } else {
                    v0 = fast_tanh(v0); v1 = fast_tanh(v1);
                    v2 = fast_tanh(v2); v3 = fast_tanh(v3);
                }
            }
            if (ROUND) {
                v0 = __uint_as_float(f2tf32(v0));
                v1 = __uint_as_float(f2tf32(v1));
                v2 = __uint_as_float(f2tf32(v2));
                v3 = __uint_as_float(f2tf32(v3));
            }
            if (EPI != EPI_RELU_SPLIT) {
                *(float2*)&C0[(size_t)row0 * NC + col]       = make_float2(v0, v1);
                *(float2*)&C0[(size_t)(row0 + 8) * NC + col] = make_float2(v2, v3);
            } else {
                if (col < splitN) {
                    *(float2*)&C0[(size_t)row0 * splitN + col]       = make_float2(v0, v1);
                    *(float2*)&C0[(size_t)(row0 + 8) * splitN + col] = make_float2(v2, v3);
                } else {
                    const int c2 = col - splitN, w2 = NC - splitN;
                    *(float2*)&C1[(size_t)row0 * w2 + c2]       = make_float2(v0, v1);
                    *(float2*)&C1[(size_t)(row0 + 8) * w2 + c2] = make_float2(v2, v3);
                }
            }
        }
    }
}

// ---------------------------------------------------------------------------
// Launch
// ---------------------------------------------------------------------------
extern "C" void kernel_launch(void* const* d_in, const int* in_sizes, int n_in,
                              void* d_out, int out_size)
{
    const float* inputs = (const float*)d_in[0];
    const float* center = (const float*)d_in[1];
    const float* mstate = (const float*)d_in[2];
    const float* W_read = (const float*)d_in[3];
    const float* W_pre  = (const float*)d_in[4];
    const float* b_pre  = (const float*)d_in[5];
    const float* Wx     = (const float*)d_in[6];
    const float* Wh     = (const float*)d_in[7];
    const float* b_rnn  = (const float*)d_in[8];
    const float* W_post = (const float*)d_in[9];
    const float* b_post = (const float*)d_in[10];

    float* out  = (float*)d_out;
    float* net  = out;
    float* o2c  = out + (size_t)B_ * OUT_;
    float* hnew = out + (size_t)B_ * (OUT_ + O2C_);

    float *WpreT, *WxT, *WhT, *WpostT, *WreadT, *ctx, *inTf, *ctrTf, *mstTf, *rnn;
    cudaGetSymbolAddress((void**)&WpreT,  g_WpreT);
    cudaGetSymbolAddress((void**)&WxT,    g_WxT);
    cudaGetSymbolAddress((void**)&WhT,    g_WhT);
    cudaGetSymbolAddress((void**)&WpostT, g_WpostT);
    cudaGetSymbolAddress((void**)&WreadT, g_WreadT);
    cudaGetSymbolAddress((void**)&ctx,    g_ctx);
    cudaGetSymbolAddress((void**)&inTf,   g_inTf);
    cudaGetSymbolAddress((void**)&ctrTf,  g_ctrTf);
    cudaGetSymbolAddress((void**)&mstTf,  g_mstTf);
    cudaGetSymbolAddress((void**)&rnn,    g_rnn);

    cudaFuncSetAttribute(tgemm<EPI_SCALE>,      cudaFuncAttributeMaxDynamicSharedMemorySize, SMEM_BYTES);
    cudaFuncSetAttribute(tgemm<EPI_RELU>,       cudaFuncAttributeMaxDynamicSharedMemorySize, SMEM_BYTES);
    cudaFuncSetAttribute(tgemm<EPI_TANH>,       cudaFuncAttributeMaxDynamicSharedMemorySize, SMEM_BYTES);
    cudaFuncSetAttribute(tgemm<EPI_RELU_SPLIT>, cudaFuncAttributeMaxDynamicSharedMemorySize, SMEM_BYTES);

    norm_part<<<64, 256>>>(W_read);
    norm_fin<<<1, 64>>>();

    // One launch: tf32-round all activations
    conv_all<<<(CV_T3 + 1023) / 1024, 256>>>(inputs, center, mstate, inTf, ctrTf, mstTf);

    // One launch: transpose+round all 5 weight matrices
    transpose_all<<<TJ4, dim3(32, 8)>>>(W_pre, Wx, Wh, W_post, W_read,
                                        WpreT, WxT, WhT, WpostT, WreadT);

    // ctx = scale * (center @ W_read)   (M=8192, N=256, K=512)
    tgemm<EPI_SCALE><<<dim3(CTX_ / BN, B_ / BM), NTHREADS, SMEM_BYTES>>>(
        ctrTf, CENTER_, WreadT, CENTER_, CENTER_,
        nullptr, 0, nullptr, 0, 0,
        nullptr, ctx, nullptr, CTX_, 0);

    // rnn_in = relu(inputs@Wpre[:512] + ctx@Wpre[512:768] + b_pre)
    //   (M=8192, N=1024, K=512+256)
    tgemm<EPI_RELU><<<dim3(FF_ / BN, B_ / BM), NTHREADS, SMEM_BYTES>>>(
        inTf, IN_, WpreT, IN_ + CTX_, IN_,
        ctx, CTX_, WpreT + IN_, IN_ + CTX_, CTX_,
        b_pre, rnn, nullptr, FF_, 0);

    // h_new = tanh(rnn@Wx + mstate@Wh + b_rnn)  (M=8192,N=1024,K=1024+1024)
    tgemm<EPI_TANH><<<dim3(RNN_ / BN, B_ / BM), NTHREADS, SMEM_BYTES>>>(
        rnn, FF_, WxT, FF_, FF_,
        mstTf, RNN_, WhT, RNN_, RNN_,
        b_rnn, hnew, nullptr, RNN_, 0);

    // module_output = relu(h_new@W_post + b_post), split  (M=8192,N=768,K=1024)
    tgemm<EPI_RELU_SPLIT><<<dim3(TOT_ / BN, B_ / BM), NTHREADS, SMEM_BYTES>>>(
        hnew, RNN_, WpostT, RNN_, RNN_,
        nullptr, 0, nullptr, 0, 0,
        b_post, net, o2c, TOT_, OUT_);
}